// round 5
// baseline (speedup 1.0000x reference)
#include <cuda_runtime.h>

#define BB 4
#define CC 64
#define HH 256
#define WW 256
#define HWN 65536
#define HO 130
#define NCHUNK 16

typedef unsigned long long ull;

// ---------------- scratch (device globals; no allocations) ----------------
__device__ float g_qrgb[BB*CC*HWN];
__device__ float g_lo [BB*CC*HH*HO];
__device__ float g_hi [BB*CC*HH*HO];
__device__ float g_s  [4][BB*CC*HO*HO];
__device__ float g_s2 [4][BB*CC*HO*HO];
__device__ float g_lo2[BB*CC*HH*HO];
__device__ float g_hi2[BB*CC*HH*HO];
__device__ float g_cvt[BB*2*CC*HWN];
__device__ float g_kvr[BB*2*CC*HWN];
__device__ float g_kvd[BB*2*CC*HWN];
__device__ float g_part[2][32][NCHUNK][80];
__device__ float g_attn[2][32][64];

// db3 filters
__constant__ float c_DEC_LO[6] = { 0.035226291882100656f, -0.08544127388224149f, -0.13501102001039084f,
                                   0.4598775021193313f,    0.8068915093133388f,   0.3326705529509569f };
__constant__ float c_DEC_HI[6] = {-0.3326705529509569f,    0.8068915093133388f,  -0.4598775021193313f,
                                  -0.13501102001039084f,   0.08544127388224149f,  0.035226291882100656f };
__constant__ float c_REC_LO[6] = { 0.3326705529509569f,    0.8068915093133388f,   0.4598775021193313f,
                                  -0.13501102001039084f,  -0.08544127388224149f,  0.035226291882100656f };
__constant__ float c_REC_HI[6] = { 0.035226291882100656f,  0.08544127388224149f, -0.13501102001039084f,
                                  -0.4598775021193313f,    0.8068915093133388f,  -0.3326705529509569f };

// ---------------- packed f32x2 helpers ----------------
__device__ __forceinline__ ull pk(float lo, float hi) {
    ull r;
    asm("mov.b64 %0, {%1, %2};" : "=l"(r) : "r"(__float_as_uint(lo)), "r"(__float_as_uint(hi)));
    return r;
}
__device__ __forceinline__ void upk(float& lo, float& hi, ull v) {
    unsigned a, b;
    asm("mov.b64 {%0, %1}, %2;" : "=r"(a), "=r"(b) : "l"(v));
    lo = __uint_as_float(a); hi = __uint_as_float(b);
}
__device__ __forceinline__ void ffma2(ull& d, ull a, ull b) {
    asm("fma.rn.f32x2 %0, %1, %2, %0;" : "+l"(d) : "l"(a), "l"(b));
}
__device__ __forceinline__ ull fmul2(ull a, ull b) {
    ull r; asm("mul.rn.f32x2 %0, %1, %2;" : "=l"(r) : "l"(a), "l"(b)); return r;
}

// ---------------- DWT rows: rgb[bc,y,0..255] -> lo,hi [bc,y,0..129] ----------------
__global__ __launch_bounds__(256) void dwt_row_k(const float* __restrict__ x) {
    int tid = blockIdx.x*256 + threadIdx.x;
    const int N = BB*CC*HH*HO;
    if (tid >= N) return;
    int j  = tid % HO;
    int y  = (tid / HO) & 255;
    int bc = tid / (HO*HH);
    const float* row = x + ((size_t)bc << 16) + (y << 8);
    float lo = 0.f, hi = 0.f;
    int base = 2*j - 4;
    #pragma unroll
    for (int i = 0; i < 6; i++) {
        int col = base + i;
        if (col >= 0 && col < WW) {
            float v = row[col];
            lo += v * c_REC_LO[i];
            hi += v * c_REC_HI[i];
        }
    }
    size_t o = (size_t)bc*(HH*HO) + y*HO + j;
    g_lo[o] = lo; g_hi[o] = hi;
}

// ---------------- DWT cols (fused): lo,hi -> 4 subbands [bc,0..129,0..129] ----------------
__global__ __launch_bounds__(256) void dwt_col_k() {
    int tid = blockIdx.x*256 + threadIdx.x;
    const int N = BB*CC*HO*HO;
    if (tid >= N) return;
    int x  = tid % HO;
    int i  = (tid / HO) % HO;
    int bc = tid / (HO*HO);
    const float* lob = g_lo + (size_t)bc*(HH*HO);
    const float* hib = g_hi + (size_t)bc*(HH*HO);
    float ll=0.f, lh=0.f, hl=0.f, hh=0.f;
    int rb = 2*i - 4;
    #pragma unroll
    for (int t = 0; t < 6; t++) {
        int r = rb + t;
        if (r >= 0 && r < HH) {
            float vl = lob[r*HO + x];
            float vh = hib[r*HO + x];
            ll += vl*c_REC_LO[t]; lh += vl*c_REC_HI[t];
            hl += vh*c_REC_LO[t]; hh += vh*c_REC_HI[t];
        }
    }
    size_t o = (size_t)bc*(HO*HO) + i*HO + x;
    g_s[0][o] = ll; g_s[1][o] = lh; g_s[2][o] = hl; g_s[3][o] = hh;
}

// ---------------- subband depthwise 3x3 (130x130, 4 subbands via blockIdx.y) ----------------
__global__ __launch_bounds__(256) void dw3_sub_k(const float* __restrict__ w1, const float* __restrict__ w5,
                                                 const float* __restrict__ w7, const float* __restrict__ w9) {
    int sub = blockIdx.y;
    const float* wt = (sub == 0) ? w1 : (sub == 1) ? w5 : (sub == 2) ? w7 : w9;
    __shared__ float sw[CC*9];
    for (int i = threadIdx.x; i < CC*9; i += 256) sw[i] = wt[i];
    __syncthreads();
    int tid = blockIdx.x*256 + threadIdx.x;
    const int N = BB*CC*HO*HO;
    if (tid >= N) return;
    int x  = tid % HO;
    int y  = (tid / HO) % HO;
    int bc = tid / (HO*HO);
    int c  = bc & 63;
    const float* base = g_s[sub] + (size_t)bc*(HO*HO);
    const float* wc = sw + c*9;
    float acc = 0.f;
    #pragma unroll
    for (int dy = -1; dy <= 1; dy++) {
        int yy = y + dy;
        if (yy < 0 || yy >= HO) continue;
        #pragma unroll
        for (int dx = -1; dx <= 1; dx++) {
            int xx = x + dx;
            if (xx < 0 || xx >= HO) continue;
            acc += base[yy*HO + xx] * wc[(dy+1)*3 + (dx+1)];
        }
    }
    g_s2[sub][(size_t)bc*(HO*HO) + y*HO + x] = acc;
}

// ---------------- IDWT cols (fused): t0..t3 -> lo2,hi2 [bc,0..255,0..129] ----------------
__global__ __launch_bounds__(256) void idwt_col_k() {
    int tid = blockIdx.x*256 + threadIdx.x;
    const int N = BB*CC*HH*HO;
    if (tid >= N) return;
    int x  = tid % HO;
    int m  = (tid / HO) & 255;
    int bc = tid / (HO*HH);
    size_t sb = (size_t)bc*(HO*HO);
    int i0 = (m & 1) ? 0 : 1;     // valid taps: i0, i0+2, i0+4
    int j0 = m >> 1;              // rows j0, j0+1, j0+2
    float lo = 0.f, hi = 0.f;
    #pragma unroll
    for (int t = 0; t < 3; t++) {
        int i = i0 + 2*t;
        size_t idx = sb + (size_t)(j0 + t)*HO + x;
        float a0 = g_s2[0][idx], a1 = g_s2[1][idx];
        float a2 = g_s2[2][idx], a3 = g_s2[3][idx];
        lo += a0*c_DEC_LO[i] + a1*c_DEC_HI[i];
        hi += a2*c_DEC_LO[i] + a3*c_DEC_HI[i];
    }
    size_t o = (size_t)bc*(HH*HO) + m*HO + x;
    g_lo2[o] = lo; g_hi2[o] = hi;
}

// ---------------- IDWT rows: lo2,hi2 -> qrgb [bc,y,0..255] ----------------
__global__ __launch_bounds__(256) void idwt_row_k() {
    int tid = blockIdx.x*256 + threadIdx.x;
    int wcol = tid & 255;
    int y    = (tid >> 8) & 255;
    int bc   = tid >> 16;
    size_t base = (size_t)bc*(HH*HO) + y*HO;
    int i0 = (wcol & 1) ? 0 : 1;
    int j0 = wcol >> 1;
    float acc = 0.f;
    #pragma unroll
    for (int t = 0; t < 3; t++) {
        int i = i0 + 2*t;
        acc += g_lo2[base + j0 + t]*c_DEC_LO[i] + g_hi2[base + j0 + t]*c_DEC_HI[i];
    }
    g_qrgb[((size_t)bc << 16) + (y << 8) + wcol] = acc;
}

// ---------------- 1x1 conv 64->128, f32x2, 4 px/thread ----------------
__global__ __launch_bounds__(256) void conv1x1_k(const float* __restrict__ in,
                                                 const float* __restrict__ w,
                                                 float* __restrict__ out) {
    __shared__ ull sw2[64*64];   // 32 KB: packed weights for one 64-output half
    int b = blockIdx.y;
    int pb = (blockIdx.x*256 + threadIdx.x)*4;
    const float* ib = in  + (size_t)b*CC*HWN + pb;
    float*       ob = out + (size_t)b*(2*CC)*HWN + pb;

    for (int half = 0; half < 2; half++) {
        for (int i = threadIdx.x; i < 4096; i += 256) {
            float wv = w[half*4096 + i];
            sw2[i] = pk(wv, wv);
        }
        __syncthreads();
        #pragma unroll 1
        for (int ot = 0; ot < 4; ot++) {
            ull a0[16], a1[16];
            #pragma unroll
            for (int o = 0; o < 16; o++) { a0[o] = 0ULL; a1[o] = 0ULL; }
            #pragma unroll 4
            for (int c = 0; c < 64; c++) {
                float4 x = *(const float4*)(ib + (size_t)c*HWN);
                ull x01 = pk(x.x, x.y), x23 = pk(x.z, x.w);
                const ull* wr = sw2 + (ot*16)*64 + c;
                #pragma unroll
                for (int o = 0; o < 16; o++) {
                    ull wv = wr[o*64];
                    ffma2(a0[o], wv, x01);
                    ffma2(a1[o], wv, x23);
                }
            }
            #pragma unroll
            for (int o = 0; o < 16; o++) {
                float4 r;
                upk(r.x, r.y, a0[o]);
                upk(r.z, r.w, a1[o]);
                *(float4*)(ob + (size_t)(half*64 + ot*16 + o)*HWN) = r;
            }
        }
        __syncthreads();
    }
}

// ---------------- depthwise 3x3 on 256x256 planes, C=128, 4 px/thread ----------------
__global__ __launch_bounds__(256) void dw3_big_k(const float* __restrict__ in,
                                                 const float* __restrict__ wt,
                                                 float* __restrict__ out) {
    __shared__ float sw[128*9];
    for (int i = threadIdx.x; i < 128*9; i += 256) sw[i] = wt[i];
    __syncthreads();
    int tid = blockIdx.x*256 + threadIdx.x;   // BB*128*256*64 threads
    int q  = tid & 63;
    int y  = (tid >> 6) & 255;
    int bc = tid >> 14;
    int c  = bc & 127;
    const float* base = in + ((size_t)bc << 16) + (y << 8) + (q << 2);
    const float* wc = sw + c*9;
    float acc0 = 0.f, acc1 = 0.f, acc2 = 0.f, acc3 = 0.f;
    #pragma unroll
    for (int r = -1; r <= 1; r++) {
        int yy = y + r;
        if (yy < 0 || yy >= HH) continue;
        const float* rp = base + (r << 8);
        float4 v = *(const float4*)rp;
        float L = (q == 0)  ? 0.f : rp[-1];
        float R = (q == 63) ? 0.f : rp[4];
        float w0 = wc[(r+1)*3], w1 = wc[(r+1)*3+1], w2 = wc[(r+1)*3+2];
        acc0 += w0*L   + w1*v.x + w2*v.y;
        acc1 += w0*v.x + w1*v.y + w2*v.z;
        acc2 += w0*v.y + w1*v.z + w2*v.w;
        acc3 += w0*v.z + w1*v.w + w2*R;
    }
    *(float4*)(out + ((size_t)bc << 16) + (y << 8) + (q << 2)) = make_float4(acc0, acc1, acc2, acc3);
}

// ---------------- Gram reduction (unchanged from passing R1) ----------------
__global__ __launch_bounds__(256) void reduce_qk_k(const float* __restrict__ q,
                                                   const float* __restrict__ kv, int which) {
    int chunk = blockIdx.x;
    int bh    = blockIdx.y;
    int b = bh >> 3, h = bh & 7;
    size_t qoff = ((size_t)b*64  + h*8)*HWN;
    size_t koff = ((size_t)b*128 + h*8)*HWN;

    float acc[64]; float qn[8]; float kn[8];
    #pragma unroll
    for (int i = 0; i < 64; i++) acc[i] = 0.f;
    #pragma unroll
    for (int i = 0; i < 8; i++) { qn[i] = 0.f; kn[i] = 0.f; }

    const int CS4 = HWN / NCHUNK / 4;
    int start = chunk * CS4;
    for (int it = threadIdx.x; it < CS4; it += blockDim.x) {
        int idx = start + it;
        float4 qv[8];
        #pragma unroll
        for (int c = 0; c < 8; c++) {
            qv[c] = ((const float4*)(q + qoff + (size_t)c*HWN))[idx];
            qn[c] += qv[c].x*qv[c].x + qv[c].y*qv[c].y + qv[c].z*qv[c].z + qv[c].w*qv[c].w;
        }
        #pragma unroll
        for (int d = 0; d < 8; d++) {
            float4 k4 = ((const float4*)(kv + koff + (size_t)d*HWN))[idx];
            kn[d] += k4.x*k4.x + k4.y*k4.y + k4.z*k4.z + k4.w*k4.w;
            #pragma unroll
            for (int c = 0; c < 8; c++)
                acc[d*8+c] += qv[c].x*k4.x + qv[c].y*k4.y + qv[c].z*k4.z + qv[c].w*k4.w;
        }
    }

    __shared__ float sm[8][80];
    int lane = threadIdx.x & 31, warp = threadIdx.x >> 5;
    #pragma unroll
    for (int v = 0; v < 64; v++) {
        float r = acc[v];
        for (int s = 16; s > 0; s >>= 1) r += __shfl_down_sync(0xffffffffu, r, s);
        if (lane == 0) sm[warp][v] = r;
    }
    #pragma unroll
    for (int v = 0; v < 8; v++) {
        float r = qn[v];
        for (int s = 16; s > 0; s >>= 1) r += __shfl_down_sync(0xffffffffu, r, s);
        if (lane == 0) sm[warp][64+v] = r;
        float r2 = kn[v];
        for (int s = 16; s > 0; s >>= 1) r2 += __shfl_down_sync(0xffffffffu, r2, s);
        if (lane == 0) sm[warp][72+v] = r2;
    }
    __syncthreads();
    if (threadIdx.x < 80) {
        float s = 0.f;
        #pragma unroll
        for (int wg = 0; wg < 8; wg++) s += sm[wg][threadIdx.x];
        g_part[which][bh][chunk][threadIdx.x] = s;
    }
}

// ---------------- finish reduction + softmax (unchanged) ----------------
__global__ void attn_k(const float* __restrict__ temp) {
    int which = blockIdx.x >> 5;
    int bh    = blockIdx.x & 31;
    int h     = bh & 7;
    __shared__ float sm[80];
    if (threadIdx.x < 80) {
        float s = 0.f;
        #pragma unroll
        for (int ch = 0; ch < NCHUNK; ch++) s += g_part[which][bh][ch][threadIdx.x];
        sm[threadIdx.x] = s;
    }
    __syncthreads();
    if (threadIdx.x < 8) {
        int c = threadIdx.x;
        float t  = temp[h];
        float nq = fmaxf(sqrtf(sm[64+c]), 1e-12f);
        float srow[8];
        #pragma unroll
        for (int d = 0; d < 8; d++) {
            float nk = fmaxf(sqrtf(sm[72+d]), 1e-12f);
            float s = sm[d*8+c] / nk;
            if (which == 0) s /= nq;
            srow[d] = s * t;
        }
        float mx = srow[0];
        #pragma unroll
        for (int d = 1; d < 8; d++) mx = fmaxf(mx, srow[d]);
        float sum = 0.f;
        #pragma unroll
        for (int d = 0; d < 8; d++) { srow[d] = __expf(srow[d]-mx); sum += srow[d]; }
        float inv = 1.f / sum;
        #pragma unroll
        for (int d = 0; d < 8; d++) g_attn[which][bh][c*8+d] = srow[d]*inv;
    }
}

// ---------------- fused epilogue (f32x2, 2 px/thread) ----------------
__global__ __launch_bounds__(256) void final_k(const float* __restrict__ wproj,
                                               float* __restrict__ out) {
    __shared__ ull sA1[512], sA2[512];   // 8 KB
    __shared__ ull sW[4096];             // 32 KB
    int b = blockIdx.y;
    for (int i = threadIdx.x; i < 512; i += 256) {
        float a1 = g_attn[0][b*8 + (i>>6)][i & 63];
        float a2 = g_attn[1][b*8 + (i>>6)][i & 63];
        sA1[i] = pk(a1, a1);
        sA2[i] = pk(a2, a2);
    }
    for (int i = threadIdx.x; i < 4096; i += 256) {
        float wv = wproj[i];
        sW[i] = pk(wv, wv);
    }
    __syncthreads();

    int n = (blockIdx.x*256 + threadIdx.x)*2;
    const float* vr = g_kvr + ((size_t)b*128 + 64)*HWN + n;
    const float* vd = g_kvd + ((size_t)b*128 + 64)*HWN + n;

    ull p[64];
    #pragma unroll 1
    for (int h = 0; h < 8; h++) {
        ull os[8], oc[8];
        #pragma unroll
        for (int c = 0; c < 8; c++) { os[c] = 0ULL; oc[c] = 0ULL; }
        #pragma unroll
        for (int d = 0; d < 8; d++) {
            float2 r2 = *(const float2*)(vr + (size_t)(h*8+d)*HWN);
            float2 d2 = *(const float2*)(vd + (size_t)(h*8+d)*HWN);
            ull rr = pk(r2.x, r2.y);
            ull dd = pk(d2.x, d2.y);
            #pragma unroll
            for (int c = 0; c < 8; c++) {
                ffma2(os[c], sA1[h*64 + c*8 + d], rr);
                ffma2(oc[c], sA2[h*64 + c*8 + d], dd);
            }
        }
        #pragma unroll
        for (int c = 0; c < 8; c++) p[h*8+c] = fmul2(os[c], oc[c]);
    }

    float* ob = out + (size_t)b*64*HWN + n;
    #pragma unroll 4
    for (int o = 0; o < 64; o++) {
        ull acc = 0ULL;
        const ull* wr = sW + o*64;
        #pragma unroll
        for (int c = 0; c < 64; c++) ffma2(acc, wr[c], p[c]);
        float2 r; upk(r.x, r.y, acc);
        *(float2*)(ob + (size_t)o*HWN) = r;
    }
}

// ---------------- host launch ----------------
extern "C" void kernel_launch(void* const* d_in, const int* in_sizes, int n_in,
                              void* d_out, int out_size) {
    const float* rgb   = (const float*)d_in[0];
    const float* depth = (const float*)d_in[1];
    const float* temp  = (const float*)d_in[2];
    const float* wqr   = (const float*)d_in[3];
    const float* wqd   = (const float*)d_in[4];
    const float* wqc   = (const float*)d_in[5];
    const float* w1    = (const float*)d_in[6];
    const float* w5    = (const float*)d_in[7];
    const float* w7    = (const float*)d_in[8];
    const float* w9    = (const float*)d_in[9];
    const float* wproj = (const float*)d_in[10];
    float* out = (float*)d_out;

    void* p;
    cudaGetSymbolAddress(&p, g_qrgb); float* qrg = (float*)p;
    cudaGetSymbolAddress(&p, g_cvt);  float* cvt = (float*)p;
    cudaGetSymbolAddress(&p, g_kvr);  float* kvr = (float*)p;
    cudaGetSymbolAddress(&p, g_kvd);  float* kvd = (float*)p;

    const int T = 256;
    int N_rowdwt = BB*CC*HH*HO;     // 8,519,680
    int N_coldwt = BB*CC*HO*HO;     // 4,326,400
    int N_full   = BB*CC*HH*WW;     // 16,777,216

    // ---- MFE ----
    dwt_row_k<<<(N_rowdwt+T-1)/T, T>>>(rgb);
    dwt_col_k<<<(N_coldwt+T-1)/T, T>>>();
    dim3 sg((N_coldwt+T-1)/T, 4);
    dw3_sub_k<<<sg, T>>>(w1, w5, w7, w9);
    idwt_col_k<<<(N_rowdwt+T-1)/T, T>>>();
    idwt_row_k<<<N_full/T, T>>>();

    // ---- kv paths ----
    dim3 cg(HWN/(T*4), BB);
    conv1x1_k<<<cg, T>>>(rgb, wqr, cvt);
    dw3_big_k<<<BB*128*HH*64/T, T>>>(cvt, wqc, kvr);
    conv1x1_k<<<cg, T>>>(depth, wqd, cvt);
    dw3_big_k<<<BB*128*HH*64/T, T>>>(cvt, wqc, kvd);

    // ---- attention statistics ----
    dim3 rg(NCHUNK, 32);
    reduce_qk_k<<<rg, T>>>(qrg, kvr, 0);
    reduce_qk_k<<<rg, T>>>(qrg, kvd, 1);
    attn_k<<<64, 128>>>(temp);

    // ---- fused epilogue ----
    dim3 fg(HWN/(T*2), BB);
    final_k<<<fg, T>>>(wproj, out);
}

// round 6
// speedup vs baseline: 1.0031x; 1.0031x over previous
#include <cuda_runtime.h>

#define BB 4
#define CC 64
#define HH 256
#define WW 256
#define HWN 65536
#define HO 130
#define NCHUNK 16

typedef unsigned long long ull;

// ---------------- scratch (device globals; no allocations) ----------------
__device__ float g_qrgb[BB*CC*HWN];
__device__ float g_lo [BB*CC*HH*HO];
__device__ float g_hi [BB*CC*HH*HO];
__device__ float g_s  [4][BB*CC*HO*HO];
__device__ float g_s2 [4][BB*CC*HO*HO];
__device__ float g_lo2[BB*CC*HH*HO];
__device__ float g_hi2[BB*CC*HH*HO];
__device__ float g_cvt[BB*2*CC*HWN];
__device__ float g_kvr[BB*2*CC*HWN];
__device__ float g_kvd[BB*2*CC*HWN];
__device__ float g_part[2][32][NCHUNK][80];
__device__ float g_attn[2][32][64];

// db3 filters
__constant__ float c_DEC_LO[6] = { 0.035226291882100656f, -0.08544127388224149f, -0.13501102001039084f,
                                   0.4598775021193313f,    0.8068915093133388f,   0.3326705529509569f };
__constant__ float c_DEC_HI[6] = {-0.3326705529509569f,    0.8068915093133388f,  -0.4598775021193313f,
                                  -0.13501102001039084f,   0.08544127388224149f,  0.035226291882100656f };
__constant__ float c_REC_LO[6] = { 0.3326705529509569f,    0.8068915093133388f,   0.4598775021193313f,
                                  -0.13501102001039084f,  -0.08544127388224149f,  0.035226291882100656f };
__constant__ float c_REC_HI[6] = { 0.035226291882100656f,  0.08544127388224149f, -0.13501102001039084f,
                                  -0.4598775021193313f,    0.8068915093133388f,  -0.3326705529509569f };

// ---------------- packed f32x2 helpers ----------------
__device__ __forceinline__ ull pk(float lo, float hi) {
    ull r;
    asm("mov.b64 %0, {%1, %2};" : "=l"(r) : "r"(__float_as_uint(lo)), "r"(__float_as_uint(hi)));
    return r;
}
__device__ __forceinline__ void upk(float& lo, float& hi, ull v) {
    unsigned a, b;
    asm("mov.b64 {%0, %1}, %2;" : "=r"(a), "=r"(b) : "l"(v));
    lo = __uint_as_float(a); hi = __uint_as_float(b);
}
__device__ __forceinline__ void ffma2(ull& d, ull a, ull b) {
    asm("fma.rn.f32x2 %0, %1, %2, %0;" : "+l"(d) : "l"(a), "l"(b));
}
__device__ __forceinline__ ull fmul2(ull a, ull b) {
    ull r; asm("mul.rn.f32x2 %0, %1, %2;" : "=l"(r) : "l"(a), "l"(b)); return r;
}

// ---------------- DWT rows: rgb[bc,y,0..255] -> lo,hi [bc,y,0..129] ----------------
__global__ __launch_bounds__(256) void dwt_row_k(const float* __restrict__ x) {
    int tid = blockIdx.x*256 + threadIdx.x;
    const int N = BB*CC*HH*HO;
    if (tid >= N) return;
    int j  = tid % HO;
    int y  = (tid / HO) & 255;
    int bc = tid / (HO*HH);
    const float* row = x + ((size_t)bc << 16) + (y << 8);
    float lo = 0.f, hi = 0.f;
    int base = 2*j - 4;
    #pragma unroll
    for (int i = 0; i < 6; i++) {
        int col = base + i;
        if (col >= 0 && col < WW) {
            float v = row[col];
            lo += v * c_REC_LO[i];
            hi += v * c_REC_HI[i];
        }
    }
    size_t o = (size_t)bc*(HH*HO) + y*HO + j;
    g_lo[o] = lo; g_hi[o] = hi;
}

// ---------------- DWT cols (fused): lo,hi -> 4 subbands [bc,0..129,0..129] ----------------
__global__ __launch_bounds__(256) void dwt_col_k() {
    int tid = blockIdx.x*256 + threadIdx.x;
    const int N = BB*CC*HO*HO;
    if (tid >= N) return;
    int x  = tid % HO;
    int i  = (tid / HO) % HO;
    int bc = tid / (HO*HO);
    const float* lob = g_lo + (size_t)bc*(HH*HO);
    const float* hib = g_hi + (size_t)bc*(HH*HO);
    float ll=0.f, lh=0.f, hl=0.f, hh=0.f;
    int rb = 2*i - 4;
    #pragma unroll
    for (int t = 0; t < 6; t++) {
        int r = rb + t;
        if (r >= 0 && r < HH) {
            float vl = lob[r*HO + x];
            float vh = hib[r*HO + x];
            ll += vl*c_REC_LO[t]; lh += vl*c_REC_HI[t];
            hl += vh*c_REC_LO[t]; hh += vh*c_REC_HI[t];
        }
    }
    size_t o = (size_t)bc*(HO*HO) + i*HO + x;
    g_s[0][o] = ll; g_s[1][o] = lh; g_s[2][o] = hl; g_s[3][o] = hh;
}

// ---------------- subband depthwise 3x3 (130x130, 4 subbands via blockIdx.y) ----------------
__global__ __launch_bounds__(256) void dw3_sub_k(const float* __restrict__ w1, const float* __restrict__ w5,
                                                 const float* __restrict__ w7, const float* __restrict__ w9) {
    int sub = blockIdx.y;
    const float* wt = (sub == 0) ? w1 : (sub == 1) ? w5 : (sub == 2) ? w7 : w9;
    __shared__ float sw[CC*9];
    for (int i = threadIdx.x; i < CC*9; i += 256) sw[i] = wt[i];
    __syncthreads();
    int tid = blockIdx.x*256 + threadIdx.x;
    const int N = BB*CC*HO*HO;
    if (tid >= N) return;
    int x  = tid % HO;
    int y  = (tid / HO) % HO;
    int bc = tid / (HO*HO);
    int c  = bc & 63;
    const float* base = g_s[sub] + (size_t)bc*(HO*HO);
    const float* wc = sw + c*9;
    float acc = 0.f;
    #pragma unroll
    for (int dy = -1; dy <= 1; dy++) {
        int yy = y + dy;
        if (yy < 0 || yy >= HO) continue;
        #pragma unroll
        for (int dx = -1; dx <= 1; dx++) {
            int xx = x + dx;
            if (xx < 0 || xx >= HO) continue;
            acc += base[yy*HO + xx] * wc[(dy+1)*3 + (dx+1)];
        }
    }
    g_s2[sub][(size_t)bc*(HO*HO) + y*HO + x] = acc;
}

// ---------------- IDWT cols (fused): t0..t3 -> lo2,hi2 [bc,0..255,0..129] ----------------
__global__ __launch_bounds__(256) void idwt_col_k() {
    int tid = blockIdx.x*256 + threadIdx.x;
    const int N = BB*CC*HH*HO;
    if (tid >= N) return;
    int x  = tid % HO;
    int m  = (tid / HO) & 255;
    int bc = tid / (HO*HH);
    size_t sb = (size_t)bc*(HO*HO);
    int i0 = (m & 1) ? 0 : 1;     // valid taps: i0, i0+2, i0+4
    int j0 = m >> 1;              // rows j0, j0+1, j0+2
    float lo = 0.f, hi = 0.f;
    #pragma unroll
    for (int t = 0; t < 3; t++) {
        int i = i0 + 2*t;
        size_t idx = sb + (size_t)(j0 + t)*HO + x;
        float a0 = g_s2[0][idx], a1 = g_s2[1][idx];
        float a2 = g_s2[2][idx], a3 = g_s2[3][idx];
        lo += a0*c_DEC_LO[i] + a1*c_DEC_HI[i];
        hi += a2*c_DEC_LO[i] + a3*c_DEC_HI[i];
    }
    size_t o = (size_t)bc*(HH*HO) + m*HO + x;
    g_lo2[o] = lo; g_hi2[o] = hi;
}

// ---------------- IDWT rows: lo2,hi2 -> qrgb [bc,y,0..255] ----------------
__global__ __launch_bounds__(256) void idwt_row_k() {
    int tid = blockIdx.x*256 + threadIdx.x;
    int wcol = tid & 255;
    int y    = (tid >> 8) & 255;
    int bc   = tid >> 16;
    size_t base = (size_t)bc*(HH*HO) + y*HO;
    int i0 = (wcol & 1) ? 0 : 1;
    int j0 = wcol >> 1;
    float acc = 0.f;
    #pragma unroll
    for (int t = 0; t < 3; t++) {
        int i = i0 + 2*t;
        acc += g_lo2[base + j0 + t]*c_DEC_LO[i] + g_hi2[base + j0 + t]*c_DEC_HI[i];
    }
    g_qrgb[((size_t)bc << 16) + (y << 8) + wcol] = acc;
}

// ---------------- 1x1 conv 64->128, f32x2, 4 px/thread ----------------
__global__ __launch_bounds__(256) void conv1x1_k(const float* __restrict__ in,
                                                 const float* __restrict__ w,
                                                 float* __restrict__ out) {
    __shared__ ull sw2[64*64];   // 32 KB: packed weights for one 64-output half
    int b = blockIdx.y;
    int pb = (blockIdx.x*256 + threadIdx.x)*4;
    const float* ib = in  + (size_t)b*CC*HWN + pb;
    float*       ob = out + (size_t)b*(2*CC)*HWN + pb;

    for (int half = 0; half < 2; half++) {
        for (int i = threadIdx.x; i < 4096; i += 256) {
            float wv = w[half*4096 + i];
            sw2[i] = pk(wv, wv);
        }
        __syncthreads();
        #pragma unroll 1
        for (int ot = 0; ot < 4; ot++) {
            ull a0[16], a1[16];
            #pragma unroll
            for (int o = 0; o < 16; o++) { a0[o] = 0ULL; a1[o] = 0ULL; }
            #pragma unroll 4
            for (int c = 0; c < 64; c++) {
                float4 x = *(const float4*)(ib + (size_t)c*HWN);
                ull x01 = pk(x.x, x.y), x23 = pk(x.z, x.w);
                const ull* wr = sw2 + (ot*16)*64 + c;
                #pragma unroll
                for (int o = 0; o < 16; o++) {
                    ull wv = wr[o*64];
                    ffma2(a0[o], wv, x01);
                    ffma2(a1[o], wv, x23);
                }
            }
            #pragma unroll
            for (int o = 0; o < 16; o++) {
                float4 r;
                upk(r.x, r.y, a0[o]);
                upk(r.z, r.w, a1[o]);
                *(float4*)(ob + (size_t)(half*64 + ot*16 + o)*HWN) = r;
            }
        }
        __syncthreads();
    }
}

// ---------------- depthwise 3x3 on 256x256 planes, C=128, 4 px/thread ----------------
__global__ __launch_bounds__(256) void dw3_big_k(const float* __restrict__ in,
                                                 const float* __restrict__ wt,
                                                 float* __restrict__ out) {
    __shared__ float sw[128*9];
    for (int i = threadIdx.x; i < 128*9; i += 256) sw[i] = wt[i];
    __syncthreads();
    int tid = blockIdx.x*256 + threadIdx.x;   // BB*128*256*64 threads
    int q  = tid & 63;
    int y  = (tid >> 6) & 255;
    int bc = tid >> 14;
    int c  = bc & 127;
    const float* base = in + ((size_t)bc << 16) + (y << 8) + (q << 2);
    const float* wc = sw + c*9;
    float acc0 = 0.f, acc1 = 0.f, acc2 = 0.f, acc3 = 0.f;
    #pragma unroll
    for (int r = -1; r <= 1; r++) {
        int yy = y + r;
        if (yy < 0 || yy >= HH) continue;
        const float* rp = base + (r << 8);
        float4 v = *(const float4*)rp;
        float L = (q == 0)  ? 0.f : rp[-1];
        float R = (q == 63) ? 0.f : rp[4];
        float w0 = wc[(r+1)*3], w1 = wc[(r+1)*3+1], w2 = wc[(r+1)*3+2];
        acc0 += w0*L   + w1*v.x + w2*v.y;
        acc1 += w0*v.x + w1*v.y + w2*v.z;
        acc2 += w0*v.y + w1*v.z + w2*v.w;
        acc3 += w0*v.z + w1*v.w + w2*R;
    }
    *(float4*)(out + ((size_t)bc << 16) + (y << 8) + (q << 2)) = make_float4(acc0, acc1, acc2, acc3);
}

// ---------------- Gram reduction (unchanged from passing R1) ----------------
__global__ __launch_bounds__(256) void reduce_qk_k(const float* __restrict__ q,
                                                   const float* __restrict__ kv, int which) {
    int chunk = blockIdx.x;
    int bh    = blockIdx.y;
    int b = bh >> 3, h = bh & 7;
    size_t qoff = ((size_t)b*64  + h*8)*HWN;
    size_t koff = ((size_t)b*128 + h*8)*HWN;

    float acc[64]; float qn[8]; float kn[8];
    #pragma unroll
    for (int i = 0; i < 64; i++) acc[i] = 0.f;
    #pragma unroll
    for (int i = 0; i < 8; i++) { qn[i] = 0.f; kn[i] = 0.f; }

    const int CS4 = HWN / NCHUNK / 4;
    int start = chunk * CS4;
    for (int it = threadIdx.x; it < CS4; it += blockDim.x) {
        int idx = start + it;
        float4 qv[8];
        #pragma unroll
        for (int c = 0; c < 8; c++) {
            qv[c] = ((const float4*)(q + qoff + (size_t)c*HWN))[idx];
            qn[c] += qv[c].x*qv[c].x + qv[c].y*qv[c].y + qv[c].z*qv[c].z + qv[c].w*qv[c].w;
        }
        #pragma unroll
        for (int d = 0; d < 8; d++) {
            float4 k4 = ((const float4*)(kv + koff + (size_t)d*HWN))[idx];
            kn[d] += k4.x*k4.x + k4.y*k4.y + k4.z*k4.z + k4.w*k4.w;
            #pragma unroll
            for (int c = 0; c < 8; c++)
                acc[d*8+c] += qv[c].x*k4.x + qv[c].y*k4.y + qv[c].z*k4.z + qv[c].w*k4.w;
        }
    }

    __shared__ float sm[8][80];
    int lane = threadIdx.x & 31, warp = threadIdx.x >> 5;
    #pragma unroll
    for (int v = 0; v < 64; v++) {
        float r = acc[v];
        for (int s = 16; s > 0; s >>= 1) r += __shfl_down_sync(0xffffffffu, r, s);
        if (lane == 0) sm[warp][v] = r;
    }
    #pragma unroll
    for (int v = 0; v < 8; v++) {
        float r = qn[v];
        for (int s = 16; s > 0; s >>= 1) r += __shfl_down_sync(0xffffffffu, r, s);
        if (lane == 0) sm[warp][64+v] = r;
        float r2 = kn[v];
        for (int s = 16; s > 0; s >>= 1) r2 += __shfl_down_sync(0xffffffffu, r2, s);
        if (lane == 0) sm[warp][72+v] = r2;
    }
    __syncthreads();
    if (threadIdx.x < 80) {
        float s = 0.f;
        #pragma unroll
        for (int wg = 0; wg < 8; wg++) s += sm[wg][threadIdx.x];
        g_part[which][bh][chunk][threadIdx.x] = s;
    }
}

// ---------------- finish reduction + softmax (unchanged) ----------------
__global__ void attn_k(const float* __restrict__ temp) {
    int which = blockIdx.x >> 5;
    int bh    = blockIdx.x & 31;
    int h     = bh & 7;
    __shared__ float sm[80];
    if (threadIdx.x < 80) {
        float s = 0.f;
        #pragma unroll
        for (int ch = 0; ch < NCHUNK; ch++) s += g_part[which][bh][ch][threadIdx.x];
        sm[threadIdx.x] = s;
    }
    __syncthreads();
    if (threadIdx.x < 8) {
        int c = threadIdx.x;
        float t  = temp[h];
        float nq = fmaxf(sqrtf(sm[64+c]), 1e-12f);
        float srow[8];
        #pragma unroll
        for (int d = 0; d < 8; d++) {
            float nk = fmaxf(sqrtf(sm[72+d]), 1e-12f);
            float s = sm[d*8+c] / nk;
            if (which == 0) s /= nq;
            srow[d] = s * t;
        }
        float mx = srow[0];
        #pragma unroll
        for (int d = 1; d < 8; d++) mx = fmaxf(mx, srow[d]);
        float sum = 0.f;
        #pragma unroll
        for (int d = 0; d < 8; d++) { srow[d] = __expf(srow[d]-mx); sum += srow[d]; }
        float inv = 1.f / sum;
        #pragma unroll
        for (int d = 0; d < 8; d++) g_attn[which][bh][c*8+d] = srow[d]*inv;
    }
}

// ---------------- fused epilogue (f32x2, 2 px/thread) ----------------
__global__ __launch_bounds__(256) void final_k(const float* __restrict__ wproj,
                                               float* __restrict__ out) {
    __shared__ ull sA1[512], sA2[512];   // 8 KB
    __shared__ ull sW[4096];             // 32 KB
    int b = blockIdx.y;
    for (int i = threadIdx.x; i < 512; i += 256) {
        float a1 = g_attn[0][b*8 + (i>>6)][i & 63];
        float a2 = g_attn[1][b*8 + (i>>6)][i & 63];
        sA1[i] = pk(a1, a1);
        sA2[i] = pk(a2, a2);
    }
    for (int i = threadIdx.x; i < 4096; i += 256) {
        float wv = wproj[i];
        sW[i] = pk(wv, wv);
    }
    __syncthreads();

    int n = (blockIdx.x*256 + threadIdx.x)*2;
    const float* vr = g_kvr + ((size_t)b*128 + 64)*HWN + n;
    const float* vd = g_kvd + ((size_t)b*128 + 64)*HWN + n;

    ull p[64];
    #pragma unroll 1
    for (int h = 0; h < 8; h++) {
        ull os[8], oc[8];
        #pragma unroll
        for (int c = 0; c < 8; c++) { os[c] = 0ULL; oc[c] = 0ULL; }
        #pragma unroll
        for (int d = 0; d < 8; d++) {
            float2 r2 = *(const float2*)(vr + (size_t)(h*8+d)*HWN);
            float2 d2 = *(const float2*)(vd + (size_t)(h*8+d)*HWN);
            ull rr = pk(r2.x, r2.y);
            ull dd = pk(d2.x, d2.y);
            #pragma unroll
            for (int c = 0; c < 8; c++) {
                ffma2(os[c], sA1[h*64 + c*8 + d], rr);
                ffma2(oc[c], sA2[h*64 + c*8 + d], dd);
            }
        }
        #pragma unroll
        for (int c = 0; c < 8; c++) p[h*8+c] = fmul2(os[c], oc[c]);
    }

    float* ob = out + (size_t)b*64*HWN + n;
    #pragma unroll 4
    for (int o = 0; o < 64; o++) {
        ull acc = 0ULL;
        const ull* wr = sW + o*64;
        #pragma unroll
        for (int c = 0; c < 64; c++) ffma2(acc, wr[c], p[c]);
        float2 r; upk(r.x, r.y, acc);
        *(float2*)(ob + (size_t)o*HWN) = r;
    }
}

// ---------------- host launch ----------------
extern "C" void kernel_launch(void* const* d_in, const int* in_sizes, int n_in,
                              void* d_out, int out_size) {
    const float* rgb   = (const float*)d_in[0];
    const float* depth = (const float*)d_in[1];
    const float* temp  = (const float*)d_in[2];
    const float* wqr   = (const float*)d_in[3];
    const float* wqd   = (const float*)d_in[4];
    const float* wqc   = (const float*)d_in[5];
    const float* w1    = (const float*)d_in[6];
    const float* w5    = (const float*)d_in[7];
    const float* w7    = (const float*)d_in[8];
    const float* w9    = (const float*)d_in[9];
    const float* wproj = (const float*)d_in[10];
    float* out = (float*)d_out;

    void* p;
    cudaGetSymbolAddress(&p, g_qrgb); float* qrg = (float*)p;
    cudaGetSymbolAddress(&p, g_cvt);  float* cvt = (float*)p;
    cudaGetSymbolAddress(&p, g_kvr);  float* kvr = (float*)p;
    cudaGetSymbolAddress(&p, g_kvd);  float* kvd = (float*)p;

    const int T = 256;
    int N_rowdwt = BB*CC*HH*HO;     // 8,519,680
    int N_coldwt = BB*CC*HO*HO;     // 4,326,400
    int N_full   = BB*CC*HH*WW;     // 16,777,216

    // ---- MFE ----
    dwt_row_k<<<(N_rowdwt+T-1)/T, T>>>(rgb);
    dwt_col_k<<<(N_coldwt+T-1)/T, T>>>();
    dim3 sg((N_coldwt+T-1)/T, 4);
    dw3_sub_k<<<sg, T>>>(w1, w5, w7, w9);
    idwt_col_k<<<(N_rowdwt+T-1)/T, T>>>();
    idwt_row_k<<<N_full/T, T>>>();

    // ---- kv paths ----
    dim3 cg(HWN/(T*4), BB);
    conv1x1_k<<<cg, T>>>(rgb, wqr, cvt);
    dw3_big_k<<<BB*128*HH*64/T, T>>>(cvt, wqc, kvr);
    conv1x1_k<<<cg, T>>>(depth, wqd, cvt);
    dw3_big_k<<<BB*128*HH*64/T, T>>>(cvt, wqc, kvd);

    // ---- attention statistics ----
    dim3 rg(NCHUNK, 32);
    reduce_qk_k<<<rg, T>>>(qrg, kvr, 0);
    reduce_qk_k<<<rg, T>>>(qrg, kvd, 1);
    attn_k<<<64, 128>>>(temp);

    // ---- fused epilogue ----
    dim3 fg(HWN/(T*2), BB);
    final_k<<<fg, T>>>(wproj, out);
}

// round 7
// speedup vs baseline: 1.0058x; 1.0027x over previous
#include <cuda_runtime.h>

#define BB 4
#define CC 64
#define HH 256
#define WW 256
#define HWN 65536
#define HO 130
#define NCHUNK 32

typedef unsigned long long ull;

// ---------------- scratch (device globals; no allocations) ----------------
__device__ float g_qrgb[BB*CC*HWN];
__device__ float g_s  [4][BB*CC*HO*HO];
__device__ float g_cvt[BB*2*CC*HWN];
__device__ float g_kvr[BB*2*CC*HWN];
__device__ float g_kvd[BB*2*CC*HWN];
__device__ float g_part[2][32][NCHUNK][80];
__device__ float g_attn[2][32][64];

// db3 filters
__constant__ float c_DEC_LO[6] = { 0.035226291882100656f, -0.08544127388224149f, -0.13501102001039084f,
                                   0.4598775021193313f,    0.8068915093133388f,   0.3326705529509569f };
__constant__ float c_DEC_HI[6] = {-0.3326705529509569f,    0.8068915093133388f,  -0.4598775021193313f,
                                  -0.13501102001039084f,   0.08544127388224149f,  0.035226291882100656f };
__constant__ float c_REC_LO[6] = { 0.3326705529509569f,    0.8068915093133388f,   0.4598775021193313f,
                                  -0.13501102001039084f,  -0.08544127388224149f,  0.035226291882100656f };
__constant__ float c_REC_HI[6] = { 0.035226291882100656f,  0.08544127388224149f, -0.13501102001039084f,
                                  -0.4598775021193313f,    0.8068915093133388f,  -0.3326705529509569f };

// ---------------- packed f32x2 helpers ----------------
__device__ __forceinline__ ull pk(float lo, float hi) {
    ull r;
    asm("mov.b64 %0, {%1, %2};" : "=l"(r) : "r"(__float_as_uint(lo)), "r"(__float_as_uint(hi)));
    return r;
}
__device__ __forceinline__ void upk(float& lo, float& hi, ull v) {
    unsigned a, b;
    asm("mov.b64 {%0, %1}, %2;" : "=r"(a), "=r"(b) : "l"(v));
    lo = __uint_as_float(a); hi = __uint_as_float(b);
}
__device__ __forceinline__ void ffma2(ull& d, ull a, ull b) {
    asm("fma.rn.f32x2 %0, %1, %2, %0;" : "+l"(d) : "l"(a), "l"(b));
}
__device__ __forceinline__ ull fmul2(ull a, ull b) {
    ull r; asm("mul.rn.f32x2 %0, %1, %2;" : "=l"(r) : "l"(a), "l"(b)); return r;
}

// ================= fused DWT (rows+cols): rgb -> 4 subbands =================
// block: (strip of 16 subband rows) x (bc). Computes lo/hi rows in smem.
__global__ __launch_bounds__(256) void mfe_front_k(const float* __restrict__ x) {
    __shared__ float sLo[36*130], sHi[36*130];
    int bc = blockIdx.y;
    int i0 = blockIdx.x * 16;
    int iCnt = min(16, HO - i0);
    int rbase = max(0, 2*i0 - 4);
    int rend  = min(HH-1, 2*(i0 + iCnt - 1) + 1);
    int nR = rend - rbase + 1;                      // <= 36
    const float* plane = x + ((size_t)bc << 16);

    for (int idx = threadIdx.x; idx < nR*130; idx += 256) {
        int rl = idx / 130, j = idx - rl*130;
        const float* row = plane + ((rbase + rl) << 8);
        float lo = 0.f, hi = 0.f;
        int base = 2*j - 4;
        #pragma unroll
        for (int s = 0; s < 6; s++) {
            int col = base + s;
            if (col >= 0 && col < WW) {
                float v = row[col];
                lo += v * c_REC_LO[s];
                hi += v * c_REC_HI[s];
            }
        }
        sLo[idx] = lo; sHi[idx] = hi;
    }
    __syncthreads();

    size_t obase = (size_t)bc * (HO*HO);
    for (int idx = threadIdx.x; idx < iCnt*130; idx += 256) {
        int il = idx / 130, xc = idx - il*130;
        int i = i0 + il;
        float ll=0.f, lh=0.f, hl=0.f, hh=0.f;
        int rb = 2*i - 4;
        #pragma unroll
        for (int t = 0; t < 6; t++) {
            int r = rb + t;
            if (r >= 0 && r < HH) {
                int rl = r - rbase;
                float vl = sLo[rl*130 + xc], vh = sHi[rl*130 + xc];
                ll += vl*c_REC_LO[t]; lh += vl*c_REC_HI[t];
                hl += vh*c_REC_LO[t]; hh += vh*c_REC_HI[t];
            }
        }
        size_t o = obase + (size_t)i*HO + xc;
        g_s[0][o]=ll; g_s[1][o]=lh; g_s[2][o]=hl; g_s[3][o]=hh;
    }
}

// ======= fused dw3(subbands) + IDWT(cols+rows): 4 subbands -> qrgb =======
// block: (strip of 32 output rows) x (bc). Dynamic smem: raw(10400)+post(9360) floats.
__global__ __launch_bounds__(256) void mfe_back_k(const float* __restrict__ w1, const float* __restrict__ w5,
                                                  const float* __restrict__ w7, const float* __restrict__ w9) {
    extern __shared__ float sdyn[];
    float* sRaw  = sdyn;              // 4 x 20 x 130 (later reused for lo2/hi2)
    float* sPost = sdyn + 10400;      // 4 x 18 x 130
    __shared__ float sW[36];

    int bc = blockIdx.y;
    int c  = bc & 63;
    int m0 = blockIdx.x * 32;
    int jp0 = m0 >> 1;                        // post rows jp0..jp0+17
    int jr0 = max(0, jp0 - 1);
    int jr1 = min(HO-1, jp0 + 18);
    int nJr = jr1 - jr0 + 1;                  // <= 20

    if (threadIdx.x < 36) {
        int s = threadIdx.x / 9, k = threadIdx.x - s*9;
        const float* wp = (s==0) ? w1 : (s==1) ? w5 : (s==2) ? w7 : w9;
        sW[threadIdx.x] = wp[c*9 + k];
    }

    // phase 1: load raw subband rows
    size_t sbase = (size_t)bc * (HO*HO);
    int nElems = 4*nJr*130;
    for (int idx = threadIdx.x; idx < nElems; idx += 256) {
        int s = idx / (nJr*130);
        int rem = idx - s*nJr*130;
        int rl = rem / 130, xc = rem - rl*130;
        sRaw[s*(20*130) + rl*130 + xc] = g_s[s][sbase + (size_t)(jr0+rl)*HO + xc];
    }
    __syncthreads();

    // phase 2: depthwise 3x3 (zero pad at global subband edges) -> sPost
    for (int idx = threadIdx.x; idx < 4*18*130; idx += 256) {
        int s = idx / (18*130);
        int rem = idx - s*(18*130);
        int pl = rem / 130, xc = rem - pl*130;
        int jglob = jp0 + pl;
        const float* wr = sW + s*9;
        const float* rb = sRaw + s*(20*130);
        float acc = 0.f;
        #pragma unroll
        for (int dy = -1; dy <= 1; dy++) {
            int jn = jglob + dy;
            if (jn < 0 || jn >= HO) continue;
            int rl = jn - jr0;
            #pragma unroll
            for (int dx = -1; dx <= 1; dx++) {
                int xn = xc + dx;
                if (xn < 0 || xn >= HO) continue;
                acc += rb[rl*130 + xn] * wr[(dy+1)*3 + (dx+1)];
            }
        }
        sPost[idx] = acc;
    }
    __syncthreads();

    // phase 3: IDWT cols -> lo2/hi2 rows (32 x 130), stored over sRaw
    float* sL2 = sRaw;          // 32*130 = 4160
    float* sH2 = sRaw + 4160;
    for (int idx = threadIdx.x; idx < 32*130; idx += 256) {
        int ml = idx / 130, xc = idx - ml*130;
        int m = m0 + ml;
        int i0f = (m & 1) ? 0 : 1;
        int jl = (m >> 1) - jp0;                  // 0..15
        float lo = 0.f, hi = 0.f;
        #pragma unroll
        for (int t = 0; t < 3; t++) {
            int fi = i0f + 2*t;
            int pr = jl + t;                       // 0..17
            float a0 = sPost[0*(18*130) + pr*130 + xc];
            float a1 = sPost[1*(18*130) + pr*130 + xc];
            float a2 = sPost[2*(18*130) + pr*130 + xc];
            float a3 = sPost[3*(18*130) + pr*130 + xc];
            lo += a0*c_DEC_LO[fi] + a1*c_DEC_HI[fi];
            hi += a2*c_DEC_LO[fi] + a3*c_DEC_HI[fi];
        }
        sL2[idx] = lo; sH2[idx] = hi;
    }
    __syncthreads();

    // phase 4: IDWT rows -> qrgb (32 x 256)
    float* oplane = g_qrgb + ((size_t)bc << 16);
    for (int idx = threadIdx.x; idx < 32*256; idx += 256) {
        int ml = idx >> 8, w = idx & 255;
        int i0f = (w & 1) ? 0 : 1;
        int j0w = w >> 1;                          // j0w+2 <= 129
        const float* lrow = sL2 + ml*130;
        const float* hrow = sH2 + ml*130;
        float acc = 0.f;
        #pragma unroll
        for (int t = 0; t < 3; t++) {
            int fi = i0f + 2*t;
            acc += lrow[j0w+t]*c_DEC_LO[fi] + hrow[j0w+t]*c_DEC_HI[fi];
        }
        oplane[((m0 + ml) << 8) + w] = acc;
    }
}

// ---------------- 1x1 conv 64->128, f32x2, 4 px/thread ----------------
__global__ __launch_bounds__(256) void conv1x1_k(const float* __restrict__ in,
                                                 const float* __restrict__ w,
                                                 float* __restrict__ out) {
    __shared__ ull sw2[64*64];
    int b = blockIdx.y;
    int pb = (blockIdx.x*256 + threadIdx.x)*4;
    const float* ib = in  + (size_t)b*CC*HWN + pb;
    float*       ob = out + (size_t)b*(2*CC)*HWN + pb;

    for (int half = 0; half < 2; half++) {
        for (int i = threadIdx.x; i < 4096; i += 256) {
            float wv = w[half*4096 + i];
            sw2[i] = pk(wv, wv);
        }
        __syncthreads();
        #pragma unroll 1
        for (int ot = 0; ot < 4; ot++) {
            ull a0[16], a1[16];
            #pragma unroll
            for (int o = 0; o < 16; o++) { a0[o] = 0ULL; a1[o] = 0ULL; }
            #pragma unroll 4
            for (int c = 0; c < 64; c++) {
                float4 x = *(const float4*)(ib + (size_t)c*HWN);
                ull x01 = pk(x.x, x.y), x23 = pk(x.z, x.w);
                const ull* wr = sw2 + (ot*16)*64 + c;
                #pragma unroll
                for (int o = 0; o < 16; o++) {
                    ull wv = wr[o*64];
                    ffma2(a0[o], wv, x01);
                    ffma2(a1[o], wv, x23);
                }
            }
            #pragma unroll
            for (int o = 0; o < 16; o++) {
                float4 r;
                upk(r.x, r.y, a0[o]);
                upk(r.z, r.w, a1[o]);
                *(float4*)(ob + (size_t)(half*64 + ot*16 + o)*HWN) = r;
            }
        }
        __syncthreads();
    }
}

// ---------------- depthwise 3x3 on 256x256 planes, C=128, 4 px/thread ----------------
__global__ __launch_bounds__(256) void dw3_big_k(const float* __restrict__ in,
                                                 const float* __restrict__ wt,
                                                 float* __restrict__ out) {
    __shared__ float sw[128*9];
    for (int i = threadIdx.x; i < 128*9; i += 256) sw[i] = wt[i];
    __syncthreads();
    int tid = blockIdx.x*256 + threadIdx.x;
    int q  = tid & 63;
    int y  = (tid >> 6) & 255;
    int bc = tid >> 14;
    int c  = bc & 127;
    const float* base = in + ((size_t)bc << 16) + (y << 8) + (q << 2);
    const float* wc = sw + c*9;
    float acc0 = 0.f, acc1 = 0.f, acc2 = 0.f, acc3 = 0.f;
    #pragma unroll
    for (int r = -1; r <= 1; r++) {
        int yy = y + r;
        if (yy < 0 || yy >= HH) continue;
        const float* rp = base + (r << 8);
        float4 v = *(const float4*)rp;
        float L = (q == 0)  ? 0.f : rp[-1];
        float R = (q == 63) ? 0.f : rp[4];
        float w0 = wc[(r+1)*3], w1 = wc[(r+1)*3+1], w2 = wc[(r+1)*3+2];
        acc0 += w0*L   + w1*v.x + w2*v.y;
        acc1 += w0*v.x + w1*v.y + w2*v.z;
        acc2 += w0*v.y + w1*v.z + w2*v.w;
        acc3 += w0*v.z + w1*v.w + w2*R;
    }
    *(float4*)(out + ((size_t)bc << 16) + (y << 8) + (q << 2)) = make_float4(acc0, acc1, acc2, acc3);
}

// ---------- fused Gram reduction: q read once, both modalities ----------
__global__ __launch_bounds__(256, 1) void reduce_qk2_k(const float* __restrict__ q,
                                                       const float* __restrict__ kvr,
                                                       const float* __restrict__ kvd) {
    int chunk = blockIdx.x;     // 0..NCHUNK-1
    int bh    = blockIdx.y;     // 0..31
    int b = bh >> 3, h = bh & 7;
    size_t qoff = ((size_t)b*64  + h*8)*HWN;
    size_t koff = ((size_t)b*128 + h*8)*HWN;

    float accr[64], accd[64], qn[8], knr[8], knd[8];
    #pragma unroll
    for (int i = 0; i < 64; i++) { accr[i] = 0.f; accd[i] = 0.f; }
    #pragma unroll
    for (int i = 0; i < 8; i++) { qn[i] = 0.f; knr[i] = 0.f; knd[i] = 0.f; }

    const int CS4 = HWN / NCHUNK / 4;   // 512 float4 per chunk
    int start = chunk * CS4;
    for (int it = threadIdx.x; it < CS4; it += blockDim.x) {
        int idx = start + it;
        float4 qv[8];
        #pragma unroll
        for (int c = 0; c < 8; c++) {
            qv[c] = ((const float4*)(q + qoff + (size_t)c*HWN))[idx];
            qn[c] += qv[c].x*qv[c].x + qv[c].y*qv[c].y + qv[c].z*qv[c].z + qv[c].w*qv[c].w;
        }
        #pragma unroll
        for (int d = 0; d < 8; d++) {
            float4 k4 = ((const float4*)(kvr + koff + (size_t)d*HWN))[idx];
            knr[d] += k4.x*k4.x + k4.y*k4.y + k4.z*k4.z + k4.w*k4.w;
            #pragma unroll
            for (int c = 0; c < 8; c++)
                accr[d*8+c] += qv[c].x*k4.x + qv[c].y*k4.y + qv[c].z*k4.z + qv[c].w*k4.w;
        }
        #pragma unroll
        for (int d = 0; d < 8; d++) {
            float4 k4 = ((const float4*)(kvd + koff + (size_t)d*HWN))[idx];
            knd[d] += k4.x*k4.x + k4.y*k4.y + k4.z*k4.z + k4.w*k4.w;
            #pragma unroll
            for (int c = 0; c < 8; c++)
                accd[d*8+c] += qv[c].x*k4.x + qv[c].y*k4.y + qv[c].z*k4.z + qv[c].w*k4.w;
        }
    }

    // sm columns: 0..63 accr, 64..71 qn, 72..79 knr, 80..143 accd, 144..151 knd
    __shared__ float sm[8][152];
    int lane = threadIdx.x & 31, warp = threadIdx.x >> 5;
    #pragma unroll
    for (int v = 0; v < 64; v++) {
        float r = accr[v];
        for (int s = 16; s > 0; s >>= 1) r += __shfl_down_sync(0xffffffffu, r, s);
        if (lane == 0) sm[warp][v] = r;
        float r2 = accd[v];
        for (int s = 16; s > 0; s >>= 1) r2 += __shfl_down_sync(0xffffffffu, r2, s);
        if (lane == 0) sm[warp][80+v] = r2;
    }
    #pragma unroll
    for (int v = 0; v < 8; v++) {
        float r = qn[v];
        for (int s = 16; s > 0; s >>= 1) r += __shfl_down_sync(0xffffffffu, r, s);
        if (lane == 0) sm[warp][64+v] = r;
        float r2 = knr[v];
        for (int s = 16; s > 0; s >>= 1) r2 += __shfl_down_sync(0xffffffffu, r2, s);
        if (lane == 0) sm[warp][72+v] = r2;
        float r3 = knd[v];
        for (int s = 16; s > 0; s >>= 1) r3 += __shfl_down_sync(0xffffffffu, r3, s);
        if (lane == 0) sm[warp][144+v] = r3;
    }
    __syncthreads();
    if (threadIdx.x < 160) {
        int which = threadIdx.x / 80;
        int t = threadIdx.x - which*80;
        int col;
        if (which == 0) col = t;
        else            col = (t < 64) ? 80 + t : (t < 72 ? t : 72 + t);  // 64..71 -> qn(64..71), 72..79 -> 144..151
        float s = 0.f;
        #pragma unroll
        for (int wg = 0; wg < 8; wg++) s += sm[wg][col];
        g_part[which][bh][chunk][t] = s;
    }
}

// ---------------- finish reduction + softmax ----------------
__global__ void attn_k(const float* __restrict__ temp) {
    int which = blockIdx.x >> 5;
    int bh    = blockIdx.x & 31;
    int h     = bh & 7;
    __shared__ float sm[80];
    if (threadIdx.x < 80) {
        float s = 0.f;
        #pragma unroll
        for (int ch = 0; ch < NCHUNK; ch++) s += g_part[which][bh][ch][threadIdx.x];
        sm[threadIdx.x] = s;
    }
    __syncthreads();
    if (threadIdx.x < 8) {
        int c = threadIdx.x;
        float t  = temp[h];
        float nq = fmaxf(sqrtf(sm[64+c]), 1e-12f);
        float srow[8];
        #pragma unroll
        for (int d = 0; d < 8; d++) {
            float nk = fmaxf(sqrtf(sm[72+d]), 1e-12f);
            float s = sm[d*8+c] / nk;
            if (which == 0) s /= nq;
            srow[d] = s * t;
        }
        float mx = srow[0];
        #pragma unroll
        for (int d = 1; d < 8; d++) mx = fmaxf(mx, srow[d]);
        float sum = 0.f;
        #pragma unroll
        for (int d = 0; d < 8; d++) { srow[d] = __expf(srow[d]-mx); sum += srow[d]; }
        float inv = 1.f / sum;
        #pragma unroll
        for (int d = 0; d < 8; d++) g_attn[which][bh][c*8+d] = srow[d]*inv;
    }
}

// ---------------- fused epilogue (f32x2, 2 px/thread) ----------------
__global__ __launch_bounds__(256) void final_k(const float* __restrict__ wproj,
                                               float* __restrict__ out) {
    __shared__ ull sA1[512], sA2[512];
    __shared__ ull sW[4096];
    int b = blockIdx.y;
    for (int i = threadIdx.x; i < 512; i += 256) {
        float a1 = g_attn[0][b*8 + (i>>6)][i & 63];
        float a2 = g_attn[1][b*8 + (i>>6)][i & 63];
        sA1[i] = pk(a1, a1);
        sA2[i] = pk(a2, a2);
    }
    for (int i = threadIdx.x; i < 4096; i += 256) {
        float wv = wproj[i];
        sW[i] = pk(wv, wv);
    }
    __syncthreads();

    int n = (blockIdx.x*256 + threadIdx.x)*2;
    const float* vr = g_kvr + ((size_t)b*128 + 64)*HWN + n;
    const float* vd = g_kvd + ((size_t)b*128 + 64)*HWN + n;

    ull p[64];
    #pragma unroll 1
    for (int h = 0; h < 8; h++) {
        ull os[8], oc[8];
        #pragma unroll
        for (int c = 0; c < 8; c++) { os[c] = 0ULL; oc[c] = 0ULL; }
        #pragma unroll
        for (int d = 0; d < 8; d++) {
            float2 r2 = *(const float2*)(vr + (size_t)(h*8+d)*HWN);
            float2 d2 = *(const float2*)(vd + (size_t)(h*8+d)*HWN);
            ull rr = pk(r2.x, r2.y);
            ull dd = pk(d2.x, d2.y);
            #pragma unroll
            for (int c = 0; c < 8; c++) {
                ffma2(os[c], sA1[h*64 + c*8 + d], rr);
                ffma2(oc[c], sA2[h*64 + c*8 + d], dd);
            }
        }
        #pragma unroll
        for (int c = 0; c < 8; c++) p[h*8+c] = fmul2(os[c], oc[c]);
    }

    float* ob = out + (size_t)b*64*HWN + n;
    #pragma unroll 4
    for (int o = 0; o < 64; o++) {
        ull acc = 0ULL;
        const ull* wr = sW + o*64;
        #pragma unroll
        for (int c = 0; c < 64; c++) ffma2(acc, wr[c], p[c]);
        float2 r; upk(r.x, r.y, acc);
        *(float2*)(ob + (size_t)o*HWN) = r;
    }
}

// ---------------- host launch ----------------
extern "C" void kernel_launch(void* const* d_in, const int* in_sizes, int n_in,
                              void* d_out, int out_size) {
    const float* rgb   = (const float*)d_in[0];
    const float* depth = (const float*)d_in[1];
    const float* temp  = (const float*)d_in[2];
    const float* wqr   = (const float*)d_in[3];
    const float* wqd   = (const float*)d_in[4];
    const float* wqc   = (const float*)d_in[5];
    const float* w1    = (const float*)d_in[6];
    const float* w5    = (const float*)d_in[7];
    const float* w7    = (const float*)d_in[8];
    const float* w9    = (const float*)d_in[9];
    const float* wproj = (const float*)d_in[10];
    float* out = (float*)d_out;

    void* p;
    cudaGetSymbolAddress(&p, g_qrgb); float* qrg = (float*)p;
    cudaGetSymbolAddress(&p, g_cvt);  float* cvt = (float*)p;
    cudaGetSymbolAddress(&p, g_kvr);  float* kvr = (float*)p;
    cudaGetSymbolAddress(&p, g_kvd);  float* kvd = (float*)p;

    const int T = 256;
    const int MFE_BACK_SMEM = (10400 + 9360) * 4;   // 79040 B
    cudaFuncSetAttribute(mfe_back_k, cudaFuncAttributeMaxDynamicSharedMemorySize, MFE_BACK_SMEM);

    // ---- MFE (2 fused kernels) ----
    dim3 fgk(9, BB*CC);                 // 9 strips of 16 subband rows
    mfe_front_k<<<fgk, T>>>(rgb);
    dim3 bgk(8, BB*CC);                 // 8 strips of 32 output rows
    mfe_back_k<<<bgk, T, MFE_BACK_SMEM>>>(w1, w5, w7, w9);

    // ---- kv paths ----
    dim3 cg(HWN/(T*4), BB);
    conv1x1_k<<<cg, T>>>(rgb, wqr, cvt);
    dw3_big_k<<<BB*128*HH*64/T, T>>>(cvt, wqc, kvr);
    conv1x1_k<<<cg, T>>>(depth, wqd, cvt);
    dw3_big_k<<<BB*128*HH*64/T, T>>>(cvt, wqc, kvd);

    // ---- attention statistics (q read once, both modalities) ----
    dim3 rg(NCHUNK, 32);
    reduce_qk2_k<<<rg, T>>>(qrg, kvr, kvd);
    attn_k<<<64, 128>>>(temp);

    // ---- fused epilogue ----
    dim3 fg(HWN/(T*2), BB);
    final_k<<<fg, T>>>(wproj, out);
}